// round 1
// baseline (speedup 1.0000x reference)
#include <cuda_runtime.h>

#define EPS 1e-8f

// Shapes: b=4, m=8, n=128, d=64
// Physical working buffer layout: P[b][m][x][y], x,y in [0,128)
__device__ float g_hg[4 * 8 * 64];
__device__ float g_hf[4 * 128 * 64];
__device__ float g_ht[4 * 128 * 64];
__device__ float g_buf[4 * 8 * 128 * 128];
__device__ float g_rowpart[4 * 8 * 128];      // per-(b,m,x) row sums (denoms for even layers)
__device__ float g_colpart[4 * 8 * 4 * 128];  // per-(b,m,chunk,y) col partials (denoms for odd layers)

// ---------------------------------------------------------------------------
// Reduction helpers (blockDim = 128 -> 4 warps)
// ---------------------------------------------------------------------------
__device__ __forceinline__ float warpReduceSum(float v) {
#pragma unroll
    for (int o = 16; o; o >>= 1) v += __shfl_xor_sync(0xffffffffu, v, o);
    return v;
}
__device__ __forceinline__ float warpReduceMax(float v) {
#pragma unroll
    for (int o = 16; o; o >>= 1) v = fmaxf(v, __shfl_xor_sync(0xffffffffu, v, o));
    return v;
}
__device__ __forceinline__ float blockReduceSum(float v, volatile float* sred, int t) {
    v = warpReduceSum(v);
    __syncthreads();
    if ((t & 31) == 0) sred[t >> 5] = v;
    __syncthreads();
    return sred[0] + sred[1] + sred[2] + sred[3];
}
__device__ __forceinline__ float blockReduceMax(float v, volatile float* sred, int t) {
    v = warpReduceMax(v);
    __syncthreads();
    if ((t & 31) == 0) sred[t >> 5] = v;
    __syncthreads();
    return fmaxf(fmaxf(sred[0], sred[1]), fmaxf(sred[2], sred[3]));
}

// ---------------------------------------------------------------------------
// k_proj: hg = groups@W1[:64], hf = cities@W1[64:128], ht = cities@W1[128:192]
// grid (264, 4), block 64.  rows: [0,8)=hg(m), [8,136)=hf(f), [136,264)=ht(t)
// ---------------------------------------------------------------------------
__global__ void k_proj(const float* __restrict__ cities, const float* __restrict__ groups,
                       const float* __restrict__ W1) {
    int b = blockIdx.y;
    int r = blockIdx.x;
    int e = threadIdx.x;
    __shared__ float xv[64];
    const float* x;
    float* out;
    int woff;
    if (r < 8) {
        x = groups + (b * 8 + r) * 64;
        out = g_hg + (b * 8 + r) * 64;
        woff = 0;
    } else if (r < 136) {
        int f = r - 8;
        x = cities + (b * 128 + f) * 64;
        out = g_hf + (b * 128 + f) * 64;
        woff = 64;
    } else {
        int t = r - 136;
        x = cities + (b * 128 + t) * 64;
        out = g_ht + (b * 128 + t) * 64;
        woff = 128;
    }
    xv[e] = x[e];
    __syncthreads();
    float acc = 0.f;
#pragma unroll
    for (int k = 0; k < 64; k++) acc += xv[k] * W1[(woff + k) * 64 + e];
    out[e] = acc;
}

// ---------------------------------------------------------------------------
// k_out: scores + max-subtract + exp, fused with layer-0 row sums.
// grid (128, 4): (f, b).  block 128 (thread = t).
// Block (b,f) owns all (m,t) for that f:
//   f==0: per-(b,m) max over t (depots_max), per-m row sums
//   f>=1: max over (m,t) (others_max), per-m row sums
// g_rowpart[b][m][f] = sum_t max(exp_val, EPS)   (layer-0 even denominator input)
// ---------------------------------------------------------------------------
__global__ void k_out(const float* __restrict__ b1, const float* __restrict__ W2,
                      const float* __restrict__ b2) {
    int b = blockIdx.y, f = blockIdx.x, t = threadIdx.x;
    __shared__ float sh_hgf[8][64];
    __shared__ float sh_w2[64];
    __shared__ float sred[4];

    for (int i = t; i < 512; i += 128) {
        int m = i >> 6, e = i & 63;
        sh_hgf[m][e] = g_hg[(b * 8 + m) * 64 + e] + g_hf[(b * 128 + f) * 64 + e] + b1[e];
    }
    if (t < 64) sh_w2[t] = W2[t];
    __syncthreads();

    float htv[64];
    const float4* htp = (const float4*)(g_ht + (b * 128 + t) * 64);
#pragma unroll
    for (int i = 0; i < 16; i++) {
        float4 v = htp[i];
        htv[i * 4] = v.x; htv[i * 4 + 1] = v.y; htv[i * 4 + 2] = v.z; htv[i * 4 + 3] = v.w;
    }
    float b2v = b2[0];

    float vals[8];
#pragma unroll
    for (int m = 0; m < 8; m++) {
        float acc = 0.f;
#pragma unroll
        for (int e = 0; e < 64; e++) {
            float h = sh_hgf[m][e] + htv[e];
            acc += fmaxf(h, 0.f) * sh_w2[e];
        }
        vals[m] = acc + b2v;
    }

    if (f == 0) {
#pragma unroll
        for (int m = 0; m < 8; m++) {
            float mx = blockReduceMax(vals[m], sred, t);
            float ev = expf(vals[m] - mx);
            g_buf[((b * 8 + m) * 128 + 0) * 128 + t] = ev;
            float s = blockReduceSum(fmaxf(ev, EPS), sred, t);
            if (t == 0) g_rowpart[(b * 8 + m) * 128 + 0] = s;
        }
    } else {
        float lm = vals[0];
#pragma unroll
        for (int m = 1; m < 8; m++) lm = fmaxf(lm, vals[m]);
        float mx = blockReduceMax(lm, sred, t);
#pragma unroll
        for (int m = 0; m < 8; m++) {
            float ev = expf(vals[m] - mx);
            g_buf[((b * 8 + m) * 128 + f) * 128 + t] = ev;
            float s = blockReduceSum(fmaxf(ev, EPS), sred, t);
            if (t == 0) g_rowpart[(b * 8 + m) * 128 + f] = s;
        }
    }
}

// ---------------------------------------------------------------------------
// F_even: even softassign layers (logical == physical on entry).
//   Scale in place: P[b,m,x,y] = max(P,EPS)/den(x)   with
//     den(0)  = rowpart[b][m][0]            (starts: per (b,m))
//     den(x)  = sum_m rowpart[b][m][x]      (nexts:  per (b,x))
//   While scaling, accumulate next (odd) layer column partials:
//     colpart[b][m][c][y] = sum_{x in chunk c} max(v, EPS)
// grid (32, 4): blockIdx.x = m*4 + chunk(c of 32 x's).  block 128 (thread = y).
// ---------------------------------------------------------------------------
__global__ void F_even() {
    int b = blockIdx.y;
    int m = blockIdx.x >> 2;
    int c = blockIdx.x & 3;
    int y = threadIdx.x;
    __shared__ float sh_rden[32];
    if (y < 32) {
        int x = c * 32 + y;
        float d;
        if (x == 0) {
            d = g_rowpart[(b * 8 + m) * 128 + 0];
        } else {
            d = 0.f;
#pragma unroll
            for (int mm = 0; mm < 8; mm++) d += g_rowpart[(b * 8 + mm) * 128 + x];
        }
        sh_rden[y] = 1.0f / d;
    }
    __syncthreads();

    float colacc = 0.f;
    float* base = g_buf + ((b * 8 + m) * 128 + c * 32) * 128 + y;
#pragma unroll
    for (int xi = 0; xi < 32; xi++) {
        float a = base[xi * 128];
        float v = fmaxf(a, EPS) * sh_rden[xi];
        base[xi * 128] = v;
        colacc += fmaxf(v, EPS);
    }
    g_colpart[((b * 8 + m) * 4 + c) * 128 + y] = colacc;
}

// ---------------------------------------------------------------------------
// F_odd: odd softassign layers (logical = transpose of physical on entry).
//   Scale in place: P[b,m,j,y] = max(P,EPS)/den(y)   with
//     den(y=0) = sum_c colpart[b][m][c][0]            (starts: per (b,m))
//     den(y)   = sum_{m,c} colpart[b][m][c][y]        (nexts:  per (b,y))
//   While scaling, produce next (even) layer row sums via smem transpose:
//     rowpart[b][m][j] = sum_y max(v, EPS)
//   Last layer writes to dst_ext (d_out) and skips the reduction.
// grid (32, 4): blockIdx.x = m*4 + chunk(cj of 32 j's).  block 128 (thread = y).
// ---------------------------------------------------------------------------
__global__ void F_odd(float* __restrict__ dst_ext, int last) {
    int b = blockIdx.y;
    int m = blockIdx.x >> 2;
    int cj = blockIdx.x & 3;
    int y = threadIdx.x;

    float d = 0.f;
    if (y == 0) {
#pragma unroll
        for (int cc = 0; cc < 4; cc++) d += g_colpart[((b * 8 + m) * 4 + cc) * 128 + 0];
    } else {
#pragma unroll
        for (int mm = 0; mm < 8; mm++)
#pragma unroll
            for (int cc = 0; cc < 4; cc++) d += g_colpart[((b * 8 + mm) * 4 + cc) * 128 + y];
    }
    float rd = 1.0f / d;

    __shared__ float sh[32][129];
    const float* src = g_buf + (b * 8 + m) * 128 * 128;
    float* dbase = (last ? dst_ext : g_buf) + (b * 8 + m) * 128 * 128;

#pragma unroll
    for (int ji = 0; ji < 32; ji++) {
        int j = cj * 32 + ji;
        float a = src[j * 128 + y];
        float v = fmaxf(a, EPS) * rd;
        dbase[j * 128 + y] = v;
        sh[ji][y] = fmaxf(v, EPS);
    }
    if (!last) {
        __syncthreads();
        if (y < 32) {
            float s = 0.f;
#pragma unroll
            for (int yy = 0; yy < 128; yy++) s += sh[y][yy];
            g_rowpart[(b * 8 + m) * 128 + cj * 32 + y] = s;
        }
    }
}

// ---------------------------------------------------------------------------
// Launch: 12 kernels total, all graph-capturable, no allocations.
// Inputs (metadata order): cities, groups, W1, b1, W2, b2 — all float32.
// ---------------------------------------------------------------------------
extern "C" void kernel_launch(void* const* d_in, const int* in_sizes, int n_in,
                              void* d_out, int out_size) {
    const float* cities = (const float*)d_in[0];
    const float* groups = (const float*)d_in[1];
    const float* W1 = (const float*)d_in[2];
    const float* b1 = (const float*)d_in[3];
    const float* W2 = (const float*)d_in[4];
    const float* b2 = (const float*)d_in[5];
    float* out = (float*)d_out;

    k_proj<<<dim3(264, 4), 64>>>(cities, groups, W1);
    k_out<<<dim3(128, 4), 128>>>(b1, W2, b2);
    for (int l = 0; l < 5; l++) {
        F_even<<<dim3(32, 4), 128>>>();
        F_odd<<<dim3(32, 4), 128>>>(out, (l == 4) ? 1 : 0);
    }
}

// round 2
// speedup vs baseline: 1.9179x; 1.9179x over previous
#include <cuda_runtime.h>
#include <cooperative_groups.h>

namespace cg = cooperative_groups;

#define EPS 1e-8f
typedef unsigned long long ull;

// Shapes: b=4, m=8, n=128, d=64
__device__ float g_hgw[4 * 8 * 64];     // hg * |w|
__device__ float g_hfw[4 * 128 * 64];   // (hf + b1) * |w|
__device__ float g_htw[4 * 128 * 64];   // ht * |w|
__device__ float g_linG[4 * 8];         // sum_e hg*w
__device__ float g_linF[4 * 128];       // sum_e (hf+b1)*w
__device__ float g_linT[4 * 128];       // sum_e ht*w
__device__ unsigned g_sgnu[64];         // sign mask of W2 per e
__device__ float g_buf[4 * 8 * 128 * 128];
__device__ float g_rowpart[4 * 8 * 128];

// ---------------------------------------------------------------------------
// Reduction helpers
// ---------------------------------------------------------------------------
__device__ __forceinline__ float warpReduceSum(float v) {
#pragma unroll
    for (int o = 16; o; o >>= 1) v += __shfl_xor_sync(0xffffffffu, v, o);
    return v;
}
__device__ __forceinline__ float warpReduceMax(float v) {
#pragma unroll
    for (int o = 16; o; o >>= 1) v = fmaxf(v, __shfl_xor_sync(0xffffffffu, v, o));
    return v;
}
__device__ __forceinline__ float blockReduceSum(float v, volatile float* sred, int t) {
    v = warpReduceSum(v);
    __syncthreads();
    if ((t & 31) == 0) sred[t >> 5] = v;
    __syncthreads();
    return sred[0] + sred[1] + sred[2] + sred[3];
}
__device__ __forceinline__ float blockReduceMax(float v, volatile float* sred, int t) {
    v = warpReduceMax(v);
    __syncthreads();
    if ((t & 31) == 0) sred[t >> 5] = v;
    __syncthreads();
    return fmaxf(fmaxf(sred[0], sred[1]), fmaxf(sred[2], sred[3]));
}

// Packed 2-MAC of the nonlinear term: acc2 += sign2 .* |gw2 + th2|
// abs+sign fused in one LOP3 per lane:  (x & 0x7fffffff) ^ signmask
__device__ __forceinline__ void mac2(ull& acc, ull gw, ull th, unsigned sl, unsigned sh2) {
    asm("{\n\t"
        ".reg .b64 h2, t2;\n\t"
        ".reg .b32 lo, hi;\n\t"
        "add.rn.f32x2 h2, %1, %2;\n\t"
        "mov.b64 {lo, hi}, h2;\n\t"
        "lop3.b32 lo, lo, 0x7fffffff, %3, 0x6A;\n\t"
        "lop3.b32 hi, hi, 0x7fffffff, %4, 0x6A;\n\t"
        "mov.b64 t2, {lo, hi};\n\t"
        "add.rn.f32x2 %0, %0, t2;\n\t"
        "}"
        : "+l"(acc)
        : "l"(gw), "l"(th), "r"(sl), "r"(sh2));
}

// ---------------------------------------------------------------------------
// k_proj: projections, pre-scaled by |W2|, plus linear dot products and signs.
// grid (264, 4), block 64.  rows: [0,8)=hg(m), [8,136)=hf(f), [136,264)=ht(t)
// ---------------------------------------------------------------------------
__global__ void k_proj(const float* __restrict__ cities, const float* __restrict__ groups,
                       const float* __restrict__ W1, const float* __restrict__ b1,
                       const float* __restrict__ W2) {
    int b = blockIdx.y;
    int r = blockIdx.x;
    int e = threadIdx.x;
    __shared__ float xv[64];
    __shared__ float sred2[2];

    const float* x;
    float* outw;
    float* lin;
    int woff;
    float badd = 0.f;
    if (r < 8) {
        x = groups + (b * 8 + r) * 64;
        outw = g_hgw + (b * 8 + r) * 64;
        lin = g_linG + b * 8 + r;
        woff = 0;
    } else if (r < 136) {
        int f = r - 8;
        x = cities + (b * 128 + f) * 64;
        outw = g_hfw + (b * 128 + f) * 64;
        lin = g_linF + b * 128 + f;
        woff = 64;
        badd = b1[e];
    } else {
        int t = r - 136;
        x = cities + (b * 128 + t) * 64;
        outw = g_htw + (b * 128 + t) * 64;
        lin = g_linT + b * 128 + t;
        woff = 128;
    }
    xv[e] = x[e];
    if (r == 0 && b == 0) g_sgnu[e] = (W2[e] < 0.f) ? 0x80000000u : 0u;
    __syncthreads();

    float acc = 0.f;
#pragma unroll
    for (int k = 0; k < 64; k++) acc += xv[k] * W1[(woff + k) * 64 + e];
    float h = acc + badd;
    float w = W2[e];
    outw[e] = h * fabsf(w);

    float p = warpReduceSum(h * w);
    if ((e & 31) == 0) sred2[e >> 5] = p;
    __syncthreads();
    if (e == 0) *lin = sred2[0] + sred2[1];
}

// ---------------------------------------------------------------------------
// k_out: scores via 0.5*lin + 0.5*sum(sign(w)*| |w|h |) + max-sub + exp,
// fused with layer-0 row sums.  grid (128, 4): (f, b).  block 128 (thread=t).
// ---------------------------------------------------------------------------
__global__ void __launch_bounds__(128) k_out(const float* __restrict__ b2) {
    int b = blockIdx.y, f = blockIdx.x, t = threadIdx.x;
    __shared__ ull sh_gw[8 * 32];      // (hgw[m] + hfw[f]) packed pairs
    __shared__ unsigned sh_sgu[64];
    __shared__ float sh_linG[8];
    __shared__ float sred[4];

    for (int idx = t; idx < 256; idx += 128) {
        int m = idx >> 5, e2 = idx & 31;
        int e = 2 * e2;
        float a0 = g_hgw[(b * 8 + m) * 64 + e] + g_hfw[(b * 128 + f) * 64 + e];
        float a1 = g_hgw[(b * 8 + m) * 64 + e + 1] + g_hfw[(b * 128 + f) * 64 + e + 1];
        sh_gw[m * 32 + e2] = (ull)__float_as_uint(a0) | ((ull)__float_as_uint(a1) << 32);
    }
    if (t < 64) sh_sgu[t] = g_sgnu[t];
    if (t < 8) sh_linG[t] = g_linG[b * 8 + t];
    __syncthreads();

    union {
        float4 f4[16];
        ull u[32];
    } tw;
    const float4* src = (const float4*)(g_htw + (b * 128 + t) * 64);
#pragma unroll
    for (int i = 0; i < 16; i++) tw.f4[i] = src[i];

    ull accs[8];
#pragma unroll
    for (int m = 0; m < 8; m++) accs[m] = 0ull;

#pragma unroll
    for (int e2 = 0; e2 < 32; e2++) {
        unsigned sl = sh_sgu[2 * e2], sh2 = sh_sgu[2 * e2 + 1];
        ull th = tw.u[e2];
#pragma unroll
        for (int m = 0; m < 8; m++) mac2(accs[m], sh_gw[m * 32 + e2], th, sl, sh2);
    }

    float linFT = g_linF[b * 128 + f] + g_linT[b * 128 + t];
    float b2v = b2[0];
    float vals[8];
#pragma unroll
    for (int m = 0; m < 8; m++) {
        float nl = __uint_as_float((unsigned)(accs[m] & 0xffffffffull)) +
                   __uint_as_float((unsigned)(accs[m] >> 32));
        vals[m] = 0.5f * (sh_linG[m] + linFT + nl) + b2v;
    }

    if (f == 0) {
#pragma unroll
        for (int m = 0; m < 8; m++) {
            float mx = blockReduceMax(vals[m], sred, t);
            float ev = expf(vals[m] - mx);
            g_buf[((b * 8 + m) * 128 + 0) * 128 + t] = ev;
            float s = blockReduceSum(fmaxf(ev, EPS), sred, t);
            if (t == 0) g_rowpart[(b * 8 + m) * 128 + 0] = s;
        }
    } else {
        float lm = vals[0];
#pragma unroll
        for (int m = 1; m < 8; m++) lm = fmaxf(lm, vals[m]);
        float mx = blockReduceMax(lm, sred, t);
#pragma unroll
        for (int m = 0; m < 8; m++) {
            float ev = expf(vals[m] - mx);
            g_buf[((b * 8 + m) * 128 + f) * 128 + t] = ev;
            float s = blockReduceSum(fmaxf(ev, EPS), sred, t);
            if (t == 0) g_rowpart[(b * 8 + m) * 128 + f] = s;
        }
    }
}

// ---------------------------------------------------------------------------
// k_soft: all 10 softassign layers in ONE kernel.
// grid 32 CTAs, cluster (8,1,1) = the 8 m-slabs of one batch b.
// 512 threads: tid = xq*128 + y, thread owns v[i] = P[x=xq*32+i][y] in regs.
// Even layers: normalize over x-index (den per x; x>0 summed over m via DSMEM).
// Odd layers:  normalize over y-index (den per y; y>0 summed over m via DSMEM).
// One cluster.sync per layer carries the cross-m sum exchange.
// ---------------------------------------------------------------------------
__global__ void __cluster_dims__(8, 1, 1) __launch_bounds__(512) k_soft(float* __restrict__ out) {
    cg::cluster_group cl = cg::this_cluster();
    const unsigned m = cl.block_rank();
    const int b = blockIdx.x >> 3;
    const int tid = threadIdx.x;
    const int y = tid & 127;
    const int xq = tid >> 7;
    const int lane = y & 31;
    const int yg = y >> 5;
    const int bm = b * 8 + (int)m;

    __shared__ float xbuf[2][128];
    __shared__ float sh_den[128];
    __shared__ float xpart[4][128];

    // Load slab into registers (coalesced)
    float v[32];
    const float* base = g_buf + (bm * 128 + xq * 32) * 128 + y;
#pragma unroll
    for (int i = 0; i < 32; i++) v[i] = base[i * 128];

    // ---- Layer 0 (even): denominators from g_rowpart (global, cross-m) ----
    if (tid < 128) {
        int x = tid;
        float d;
        if (x == 0) {
            d = g_rowpart[bm * 128];
        } else {
            d = 0.f;
#pragma unroll
            for (int mm = 0; mm < 8; mm++) d += g_rowpart[(b * 8 + mm) * 128 + x];
        }
        sh_den[x] = 1.0f / d;
    }
    __syncthreads();
    {
        float colacc = 0.f;
#pragma unroll
        for (int i = 0; i < 32; i++) {
            float s = fmaxf(v[i], EPS) * sh_den[xq * 32 + i];
            v[i] = s;
            colacc += fmaxf(s, EPS);
        }
        xpart[xq][y] = colacc;
        __syncthreads();
        if (tid < 128)
            xbuf[0][tid] = xpart[0][tid] + xpart[1][tid] + xpart[2][tid] + xpart[3][tid];
    }
    cl.sync();

    // ---- Layers 1..9 ----
#pragma unroll 1
    for (int l = 1; l < 10; l++) {
        int rb = (l - 1) & 1;
        int wb = l & 1;

        // denominators: index 0 uses own (per b,m) sum; others sum over m
        if (tid < 128) {
            float d;
            if (tid == 0) {
                d = xbuf[rb][0];
            } else {
                d = 0.f;
#pragma unroll
                for (int mm = 0; mm < 8; mm++) {
                    const float* p = cl.map_shared_rank(&xbuf[rb][0], mm);
                    d += p[tid];
                }
            }
            sh_den[tid] = 1.0f / d;
        }
        __syncthreads();

        if (l & 1) {
            // odd layer: den indexed by y (one scalar per thread)
            float rdy = sh_den[y];
            if (l == 9) {
                float* obase = out + (bm * 128 + xq * 32) * 128 + y;
#pragma unroll
                for (int i = 0; i < 32; i++) obase[i * 128] = fmaxf(v[i], EPS) * rdy;
                cl.sync();  // keep SMEM alive until all peers finished DSMEM reads
                return;
            }
#pragma unroll
            for (int i = 0; i < 32; i++) v[i] = fmaxf(v[i], EPS) * rdy;

            // row sums over y: butterfly per register, lane i keeps x = xq*32+i
            float rpart = 0.f;
#pragma unroll
            for (int i = 0; i < 32; i++) {
                float s = fmaxf(v[i], EPS);
#pragma unroll
                for (int o = 16; o; o >>= 1) s += __shfl_xor_sync(0xffffffffu, s, o);
                if (lane == i) rpart = s;
            }
            xpart[yg][xq * 32 + lane] = rpart;
            __syncthreads();
            if (tid < 128)
                xbuf[wb][tid] = xpart[0][tid] + xpart[1][tid] + xpart[2][tid] + xpart[3][tid];
        } else {
            // even layer: den indexed by x (varies per register)
            float colacc = 0.f;
#pragma unroll
            for (int i = 0; i < 32; i++) {
                float s = fmaxf(v[i], EPS) * sh_den[xq * 32 + i];
                v[i] = s;
                colacc += fmaxf(s, EPS);
            }
            xpart[xq][y] = colacc;
            __syncthreads();
            if (tid < 128)
                xbuf[wb][tid] = xpart[0][tid] + xpart[1][tid] + xpart[2][tid] + xpart[3][tid];
        }
        cl.sync();
    }
}

// ---------------------------------------------------------------------------
// Launch: 3 kernels total.
// Inputs: cities, groups, W1, b1, W2, b2 — all float32.
// ---------------------------------------------------------------------------
extern "C" void kernel_launch(void* const* d_in, const int* in_sizes, int n_in,
                              void* d_out, int out_size) {
    const float* cities = (const float*)d_in[0];
    const float* groups = (const float*)d_in[1];
    const float* W1 = (const float*)d_in[2];
    const float* b1 = (const float*)d_in[3];
    const float* W2 = (const float*)d_in[4];
    const float* b2 = (const float*)d_in[5];
    float* out = (float*)d_out;

    k_proj<<<dim3(264, 4), 64>>>(cities, groups, W1, b1, W2);
    k_out<<<dim3(128, 4), 128>>>(b2);
    k_soft<<<32, 512>>>(out);
}